// round 15
// baseline (speedup 1.0000x reference)
#include <cuda_runtime.h>
#include <cstdint>

#define NN 100000
#define EE 1600000
#define FIN 128
#define HH 64

__device__ float g_h [(size_t)NN * HH];
__device__ float g_k [(size_t)NN * HH];
__device__ float g_qv[(size_t)NN * HH * 2];   // interleaved (q, v) per feature
__device__ float g_s [(size_t)NN * HH];

__device__ int g_cnt[NN];
__device__ int g_rowptr[NN + 1];
__device__ int g_cursor[NN];
__device__ int g_col[EE];
__device__ int g_bsum[128];

// ---- XLA:CPU GenerateVF32Exp (Pommier structure) WITH FMA contraction ----
// FROZEN: this exact op sequence produced rel_err 1.67e-7. Do not alter.
__device__ __forceinline__ float xla_exp(float _x) {
    float x = fminf(_x, 88.3762626647950f);
    x = fmaxf(x, -88.3762626647949f);
    float fx = floorf(__fmaf_rn(x, 1.44269504088896341f, 0.5f));
    x = __fmaf_rn(fx, -0.693359375f, x);
    x = __fmaf_rn(fx, 2.12194440e-4f, x);
    float z = __fmul_rn(x, x);
    float y = 1.9875691500E-4f;
    y = __fmaf_rn(y, x, 1.3981999507E-3f);
    y = __fmaf_rn(y, x, 8.3334519073E-3f);
    y = __fmaf_rn(y, x, 4.1665795894E-2f);
    y = __fmaf_rn(y, x, 1.6666665459E-1f);
    y = __fmaf_rn(y, x, 5.0000001201E-1f);
    y = __fmaf_rn(y, z, x);
    y = __fadd_rn(1.0f, y);
    int n = (int)fx;
    float s = __int_as_float((n + 127) << 23);
    float r = __fmul_rn(y, s);
    return fmaxf(r, _x);
}
__device__ __forceinline__ float xla_logistic(float x) {
    float e = xla_exp(-x);
    float d = __fadd_rn(1.0f, e);
    return __fdiv_rn(1.0f, d);
}
__device__ __forceinline__ float lrelu(float x) {
    return (x >= 0.f) ? x : __fmul_rn(0.01f, x);
}

// ---- CSR build (deterministic) ----
__global__ void zero_counts_kernel() {
    int i = blockIdx.x * blockDim.x + threadIdx.x;
    if (i < NN) g_cnt[i] = 0;
}
__global__ void hist_kernel(const int* __restrict__ dst) {
    int e = blockIdx.x * blockDim.x + threadIdx.x;
    if (e < EE) atomicAdd(&g_cnt[dst[e]], 1);
}
__global__ void scan_block_kernel() {
    __shared__ int sh[1024];
    int i = blockIdx.x * 1024 + threadIdx.x;
    int v = (i < NN) ? g_cnt[i] : 0;
    sh[threadIdx.x] = v;
    __syncthreads();
    for (int off = 1; off < 1024; off <<= 1) {
        int t = 0;
        if (threadIdx.x >= off) t = sh[threadIdx.x - off];
        __syncthreads();
        sh[threadIdx.x] += t;
        __syncthreads();
    }
    if (i < NN) g_rowptr[i] = sh[threadIdx.x] - v;
    if (threadIdx.x == 1023) g_bsum[blockIdx.x] = sh[1023];
}
__global__ void scan_sums_kernel(int nblocks) {
    if (threadIdx.x == 0 && blockIdx.x == 0) {
        int run = 0;
        for (int b = 0; b < nblocks; b++) { int t = g_bsum[b]; g_bsum[b] = run; run += t; }
    }
}
__global__ void add_offsets_kernel() {
    int i = blockIdx.x * 1024 + threadIdx.x;
    if (i < NN) {
        int r = g_rowptr[i] + g_bsum[blockIdx.x];
        g_rowptr[i] = r;
        g_cursor[i] = r;
    }
    if (i == 0) g_rowptr[NN] = EE;
}
__global__ void scatter_kernel(const int* __restrict__ dst) {
    int e = blockIdx.x * blockDim.x + threadIdx.x;
    if (e < EE) {
        int pos = atomicAdd(&g_cursor[dst[e]], 1);
        g_col[pos] = e;
    }
}
__global__ void sort_rows_kernel() {
    int n = blockIdx.x * blockDim.x + threadIdx.x;
    if (n >= NN) return;
    int beg = g_rowptr[n], end = g_rowptr[n + 1];
    for (int i = beg + 1; i < end; i++) {
        int key = g_col[i];
        int j = i - 1;
        while (j >= beg && g_col[j] > key) { g_col[j + 1] = g_col[j]; j--; }
        g_col[j + 1] = key;
    }
}
__global__ void remap_kernel(const int* __restrict__ src) {
    int p = blockIdx.x * blockDim.x + threadIdx.x;
    if (p < EE) g_col[p] = src[g_col[p]];
}

// ---- fused k/q/v/s GEMM: 64 rows x 256 cols per block, 8x8 per thread.
// Per output: single accumulator, ascending k, __fmaf_rn — BIT-IDENTICAL
// accumulation order to the passing r14 kernel. ----
__global__ __launch_bounds__(256) void gemm_kqvs_kernel(
    const float* __restrict__ A, int K, const float* __restrict__ W)
{
    __shared__ float Wb[32][256];   // 32KB: Wb[kk][c], c in [0,256) over 4 mats
    __shared__ float Ab[64][32];    // 8KB:  Ab[r][kk]

    const int row0 = blockIdx.x * 64;
    const int tid  = threadIdx.x;
    const int cg   = tid & 31;      // col group: 8 cols each
    const int rg   = tid >> 5;      // row group: 8 rows each (warp = one rg)
    const int c0   = cg * 8;
    const int r0   = rg * 8;

    float acc[8][8];
#pragma unroll
    for (int i = 0; i < 8; i++)
#pragma unroll
        for (int j = 0; j < 8; j++) acc[i][j] = 0.f;

    for (int kc = 0; kc < K; kc += 32) {
        // W chunk: Wb[kk][c] = W[m][kc+kk][col], m=c>>6, col=c&63
        for (int idx = tid; idx < 32 * 256; idx += 256) {
            int kk = idx >> 8, c = idx & 255;
            int m = c >> 6, col = c & 63;
            Wb[kk][c] = W[((size_t)m * K + (kc + kk)) * 64 + col];
        }
        // A chunk: coalesced rows of 32 floats
        for (int idx = tid; idx < 64 * 32; idx += 256) {
            int r = idx >> 5, kk = idx & 31;
            int node = row0 + r;
            Ab[r][kk] = (node < NN) ? A[(size_t)node * K + kc + kk] : 0.f;
        }
        __syncthreads();

#pragma unroll 4
        for (int kk = 0; kk < 32; kk++) {
            float w[8];
#pragma unroll
            for (int j = 0; j < 8; j++) w[j] = Wb[kk][c0 + j];
#pragma unroll
            for (int i = 0; i < 8; i++) {
                float a = Ab[r0 + i][kk];      // broadcast within warp
#pragma unroll
                for (int j = 0; j < 8; j++)
                    acc[i][j] = __fmaf_rn(a, w[j], acc[i][j]);
            }
        }
        __syncthreads();
    }

#pragma unroll
    for (int i = 0; i < 8; i++) {
        int node = row0 + r0 + i;
        if (node >= NN) continue;
#pragma unroll
        for (int j = 0; j < 8; j++) {
            int c = c0 + j;
            int m = c >> 6, col = c & 63;
            float val = acc[i][j];
            size_t o = (size_t)node * 64 + col;
            if (m == 0)      g_k[o] = val;
            else if (m == 1) g_qv[o * 2] = val;       // q
            else if (m == 2) g_qv[o * 2 + 1] = val;   // v
            else             g_s[o] = val;
        }
    }
}

// ---- edge kernel: warp per dst node; pair-unrolled, loads hoisted.
// Accumulation remains STRICTLY sequential ascending-edge fadds. ----
__global__ __launch_bounds__(256) void edge_kernel(const float* __restrict__ bias) {
    int gw = (blockIdx.x * blockDim.x + threadIdx.x) >> 5;
    int lane = threadIdx.x & 31;
    if (gw >= NN) return;
    const size_t base = (size_t)gw * 64;
    float k0 = g_k[base + lane];
    float k1 = g_k[base + lane + 32];
    float a0 = 0.f, a1 = 0.f;
    int beg = g_rowptr[gw], end = g_rowptr[gw + 1];
    int cnt = end - beg;
    int e = beg;
    int e2 = beg + (cnt & ~1);
    for (; e < e2; e += 2) {
        int sA = __ldg(&g_col[e]);
        int sB = __ldg(&g_col[e + 1]);
        const float2* pA = (const float2*)&g_qv[(size_t)sA * 128];
        const float2* pB = (const float2*)&g_qv[(size_t)sB * 128];
        float2 A0 = __ldg(&pA[lane]);
        float2 A1 = __ldg(&pA[lane + 32]);
        float2 B0 = __ldg(&pB[lane]);
        float2 B1 = __ldg(&pB[lane + 32]);
        float gA0 = xla_logistic(__fadd_rn(k0, A0.x));
        float gA1 = xla_logistic(__fadd_rn(k1, A1.x));
        a0 = __fadd_rn(a0, __fmul_rn(gA0, A0.y));
        a1 = __fadd_rn(a1, __fmul_rn(gA1, A1.y));
        float gB0 = xla_logistic(__fadd_rn(k0, B0.x));
        float gB1 = xla_logistic(__fadd_rn(k1, B1.x));
        a0 = __fadd_rn(a0, __fmul_rn(gB0, B0.y));
        a1 = __fadd_rn(a1, __fmul_rn(gB1, B1.y));
    }
    if (e < end) {
        int sA = __ldg(&g_col[e]);
        const float2* pA = (const float2*)&g_qv[(size_t)sA * 128];
        float2 A0 = __ldg(&pA[lane]);
        float2 A1 = __ldg(&pA[lane + 32]);
        float gA0 = xla_logistic(__fadd_rn(k0, A0.x));
        float gA1 = xla_logistic(__fadd_rn(k1, A1.x));
        a0 = __fadd_rn(a0, __fmul_rn(gA0, A0.y));
        a1 = __fadd_rn(a1, __fmul_rn(gA1, A1.y));
    }
    float b0 = bias[lane], b1 = bias[lane + 32];
    g_h[base + lane]      = lrelu(__fadd_rn(__fadd_rn(g_s[base + lane], a0), b0));
    g_h[base + lane + 32] = lrelu(__fadd_rn(__fadd_rn(g_s[base + lane + 32], a1), b1));
}

// ---- output projection (FROZEN numerics) ----
__global__ __launch_bounds__(256) void out_gemm_kernel(
    const float* __restrict__ Wo, const float* __restrict__ bo, float* __restrict__ out)
{
    __shared__ float Ws[64 * 16];
    __shared__ float As[16][64];
    int tid = threadIdx.x;
    for (int idx = tid; idx < 64 * 16; idx += 256) Ws[idx] = Wo[idx];
    int row0 = blockIdx.x * 16;
    for (int idx = tid; idx < 16 * 64; idx += 256) {
        int r = idx >> 6, c = idx & 63;
        int node = row0 + r;
        As[r][c] = (node < NN) ? g_h[(size_t)node * 64 + c] : 0.f;
    }
    __syncthreads();
    int r = tid >> 4, c = tid & 15;
    float acc = 0.f;
#pragma unroll
    for (int k = 0; k < 64; k++) acc = __fmaf_rn(As[r][k], Ws[k * 16 + c], acc);
    int node = row0 + r;
    if (node < NN) out[(size_t)node * 16 + c] = __fadd_rn(acc, bo[c]);
}

extern "C" void kernel_launch(void* const* d_in, const int* in_sizes, int n_in,
                              void* d_out, int out_size)
{
    const float *x = 0, *W_in = 0, *b_in = 0, *W_h = 0, *b_h = 0, *W_out = 0, *b_out = 0;
    const int* ei = 0;
    for (int i = 0; i < n_in; i++) {
        switch (in_sizes[i]) {
            case 12800000: x = (const float*)d_in[i]; break;
            case 3200000: ei = (const int*)d_in[i]; break;
            case 32768: W_in = (const float*)d_in[i]; break;
            case 64: b_in = (const float*)d_in[i]; break;
            case 65536: W_h = (const float*)d_in[i]; break;
            case 256: b_h = (const float*)d_in[i]; break;
            case 1024: W_out = (const float*)d_in[i]; break;
            case 16: b_out = (const float*)d_in[i]; break;
        }
    }
    float* out = (float*)d_out;
    const int* src = ei;
    const int* dst = ei + EE;

    float* hptr = nullptr;
    cudaGetSymbolAddress((void**)&hptr, g_h);

    int tb = 256;
    zero_counts_kernel<<<(NN + tb - 1) / tb, tb>>>();
    hist_kernel<<<(EE + tb - 1) / tb, tb>>>(dst);
    int nb = (NN + 1023) / 1024;
    scan_block_kernel<<<nb, 1024>>>();
    scan_sums_kernel<<<1, 32>>>(nb);
    add_offsets_kernel<<<nb, 1024>>>();
    scatter_kernel<<<(EE + tb - 1) / tb, tb>>>(dst);
    sort_rows_kernel<<<(NN + tb - 1) / tb, tb>>>();
    remap_kernel<<<(EE + tb - 1) / tb, tb>>>(src);

    int gblocks = (NN + 63) / 64;
    int eblocks = (NN * 32 + 255) / 256;

    gemm_kqvs_kernel<<<gblocks, 256>>>(x, FIN, W_in);
    edge_kernel<<<eblocks, 256>>>(b_in);
    for (int rep = 0; rep < 3; rep++)
        for (int l = 0; l < 4; l++) {
            gemm_kqvs_kernel<<<gblocks, 256>>>(hptr, HH, W_h + (size_t)l * 4 * HH * HH);
            edge_kernel<<<eblocks, 256>>>(b_h + l * HH);
        }
    out_gemm_kernel<<<(NN + 15) / 16, 256>>>(W_out, b_out, out);
}

// round 16
// speedup vs baseline: 1.2622x; 1.2622x over previous
#include <cuda_runtime.h>
#include <cstdint>

#define NN 100000
#define EE 1600000
#define FIN 128
#define HH 64

__device__ float g_h [(size_t)NN * HH];
__device__ float g_k [(size_t)NN * HH];
__device__ float g_qv[(size_t)NN * HH * 2];   // interleaved (q, v) per feature
__device__ float g_s [(size_t)NN * HH];

__device__ int g_cnt[NN];
__device__ int g_rowptr[NN + 1];
__device__ int g_cursor[NN];
__device__ int g_col[EE];
__device__ int g_bsum[128];

// ---- XLA:CPU GenerateVF32Exp (Pommier structure) WITH FMA contraction ----
// FROZEN: this exact op sequence produced rel_err 1.67e-7. Do not alter.
__device__ __forceinline__ float xla_exp(float _x) {
    float x = fminf(_x, 88.3762626647950f);
    x = fmaxf(x, -88.3762626647949f);
    float fx = floorf(__fmaf_rn(x, 1.44269504088896341f, 0.5f));
    x = __fmaf_rn(fx, -0.693359375f, x);
    x = __fmaf_rn(fx, 2.12194440e-4f, x);
    float z = __fmul_rn(x, x);
    float y = 1.9875691500E-4f;
    y = __fmaf_rn(y, x, 1.3981999507E-3f);
    y = __fmaf_rn(y, x, 8.3334519073E-3f);
    y = __fmaf_rn(y, x, 4.1665795894E-2f);
    y = __fmaf_rn(y, x, 1.6666665459E-1f);
    y = __fmaf_rn(y, x, 5.0000001201E-1f);
    y = __fmaf_rn(y, z, x);
    y = __fadd_rn(1.0f, y);
    int n = (int)fx;
    float s = __int_as_float((n + 127) << 23);
    float r = __fmul_rn(y, s);
    return fmaxf(r, _x);
}
__device__ __forceinline__ float xla_logistic(float x) {
    float e = xla_exp(-x);
    float d = __fadd_rn(1.0f, e);
    return __fdiv_rn(1.0f, d);
}
__device__ __forceinline__ float lrelu(float x) {
    return (x >= 0.f) ? x : __fmul_rn(0.01f, x);
}

// ---- CSR build (deterministic) ----
__global__ void zero_counts_kernel() {
    int i = blockIdx.x * blockDim.x + threadIdx.x;
    if (i < NN) g_cnt[i] = 0;
}
__global__ void hist_kernel(const int* __restrict__ dst) {
    int e = blockIdx.x * blockDim.x + threadIdx.x;
    if (e < EE) atomicAdd(&g_cnt[dst[e]], 1);
}
__global__ void scan_block_kernel() {
    __shared__ int sh[1024];
    int i = blockIdx.x * 1024 + threadIdx.x;
    int v = (i < NN) ? g_cnt[i] : 0;
    sh[threadIdx.x] = v;
    __syncthreads();
    for (int off = 1; off < 1024; off <<= 1) {
        int t = 0;
        if (threadIdx.x >= off) t = sh[threadIdx.x - off];
        __syncthreads();
        sh[threadIdx.x] += t;
        __syncthreads();
    }
    if (i < NN) g_rowptr[i] = sh[threadIdx.x] - v;
    if (threadIdx.x == 1023) g_bsum[blockIdx.x] = sh[1023];
}
__global__ void scan_sums_kernel(int nblocks) {
    if (threadIdx.x == 0 && blockIdx.x == 0) {
        int run = 0;
        for (int b = 0; b < nblocks; b++) { int t = g_bsum[b]; g_bsum[b] = run; run += t; }
    }
}
__global__ void add_offsets_kernel() {
    int i = blockIdx.x * 1024 + threadIdx.x;
    if (i < NN) {
        int r = g_rowptr[i] + g_bsum[blockIdx.x];
        g_rowptr[i] = r;
        g_cursor[i] = r;
    }
    if (i == 0) g_rowptr[NN] = EE;
}
__global__ void scatter_kernel(const int* __restrict__ dst) {
    int e = blockIdx.x * blockDim.x + threadIdx.x;
    if (e < EE) {
        int pos = atomicAdd(&g_cursor[dst[e]], 1);
        g_col[pos] = e;
    }
}
__global__ void sort_rows_kernel() {
    int n = blockIdx.x * blockDim.x + threadIdx.x;
    if (n >= NN) return;
    int beg = g_rowptr[n], end = g_rowptr[n + 1];
    for (int i = beg + 1; i < end; i++) {
        int key = g_col[i];
        int j = i - 1;
        while (j >= beg && g_col[j] > key) { g_col[j + 1] = g_col[j]; j--; }
        g_col[j + 1] = key;
    }
}
__global__ void remap_kernel(const int* __restrict__ src) {
    int p = blockIdx.x * blockDim.x + threadIdx.x;
    if (p < EE) g_col[p] = src[g_col[p]];
}

// ---- fused k/q/v/s GEMM: r14 PROVEN tile (32 rows x 128 cols, 4x4/thread,
// conflict-free lane-stride-1 W loads). Only the epilogue addresses changed
// (q,v -> interleaved g_qv). Accumulation arithmetic bit-identical. ----
__global__ __launch_bounds__(256) void gemm_kqvs_kernel(
    const float* __restrict__ A, int K, const float* __restrict__ W)
{
    __shared__ float Wb[64][128];
    __shared__ float Ab[32][64];
    const int half = blockIdx.y;
    const int row0 = blockIdx.x * 32;
    const int tid = threadIdx.x;
    const int warp = tid >> 5;
    const int lane = tid & 31;

    float acc[4][4];
#pragma unroll
    for (int r = 0; r < 4; r++)
#pragma unroll
        for (int j = 0; j < 4; j++) acc[r][j] = 0.f;

    for (int kc = 0; kc < K; kc += 64) {
        for (int idx = tid; idx < 64 * 128; idx += 256) {
            int kk = idx >> 7, c = idx & 127;
            int m = half * 2 + (c >> 6);
            Wb[kk][c] = W[((size_t)m * K + (kc + kk)) * 64 + (c & 63)];
        }
        for (int idx = tid; idx < 32 * 64; idx += 256) {
            int r = idx >> 6, cc = idx & 63;
            int node = row0 + r;
            Ab[r][cc] = (node < NN) ? A[(size_t)node * K + kc + cc] : 0.f;
        }
        __syncthreads();
#pragma unroll
        for (int kk = 0; kk < 64; kk++) {
            float a0 = Ab[warp * 4 + 0][kk];
            float a1 = Ab[warp * 4 + 1][kk];
            float a2 = Ab[warp * 4 + 2][kk];
            float a3 = Ab[warp * 4 + 3][kk];
            float w0 = Wb[kk][lane];
            float w1 = Wb[kk][lane + 32];
            float w2 = Wb[kk][lane + 64];
            float w3 = Wb[kk][lane + 96];
            acc[0][0] = __fmaf_rn(a0, w0, acc[0][0]); acc[0][1] = __fmaf_rn(a0, w1, acc[0][1]);
            acc[0][2] = __fmaf_rn(a0, w2, acc[0][2]); acc[0][3] = __fmaf_rn(a0, w3, acc[0][3]);
            acc[1][0] = __fmaf_rn(a1, w0, acc[1][0]); acc[1][1] = __fmaf_rn(a1, w1, acc[1][1]);
            acc[1][2] = __fmaf_rn(a1, w2, acc[1][2]); acc[1][3] = __fmaf_rn(a1, w3, acc[1][3]);
            acc[2][0] = __fmaf_rn(a2, w0, acc[2][0]); acc[2][1] = __fmaf_rn(a2, w1, acc[2][1]);
            acc[2][2] = __fmaf_rn(a2, w2, acc[2][2]); acc[2][3] = __fmaf_rn(a2, w3, acc[2][3]);
            acc[3][0] = __fmaf_rn(a3, w0, acc[3][0]); acc[3][1] = __fmaf_rn(a3, w1, acc[3][1]);
            acc[3][2] = __fmaf_rn(a3, w2, acc[3][2]); acc[3][3] = __fmaf_rn(a3, w3, acc[3][3]);
        }
        __syncthreads();
    }
#pragma unroll
    for (int r = 0; r < 4; r++) {
        int node = row0 + warp * 4 + r;
        if (node >= NN) continue;
#pragma unroll
        for (int j = 0; j < 4; j++) {
            int c = lane + 32 * j;
            int m = half * 2 + (c >> 6);
            int col = c & 63;
            float val = acc[r][j];
            size_t o = (size_t)node * 64 + col;
            if (m == 0)      g_k[o] = val;
            else if (m == 1) g_qv[o * 2] = val;       // q
            else if (m == 2) g_qv[o * 2 + 1] = val;   // v
            else             g_s[o] = val;
        }
    }
}

// ---- edge kernel: warp per dst node; float2 (q,v) gathers, pair-unrolled,
// loads hoisted. Accumulation STRICTLY sequential ascending-edge fadds. ----
__global__ __launch_bounds__(256) void edge_kernel(const float* __restrict__ bias) {
    int gw = (blockIdx.x * blockDim.x + threadIdx.x) >> 5;
    int lane = threadIdx.x & 31;
    if (gw >= NN) return;
    const size_t base = (size_t)gw * 64;
    float k0 = g_k[base + lane];
    float k1 = g_k[base + lane + 32];
    float a0 = 0.f, a1 = 0.f;
    int beg = g_rowptr[gw], end = g_rowptr[gw + 1];
    int cnt = end - beg;
    int e = beg;
    int e2 = beg + (cnt & ~1);
    for (; e < e2; e += 2) {
        int sA = __ldg(&g_col[e]);
        int sB = __ldg(&g_col[e + 1]);
        const float2* pA = (const float2*)&g_qv[(size_t)sA * 128];
        const float2* pB = (const float2*)&g_qv[(size_t)sB * 128];
        float2 A0 = __ldg(&pA[lane]);
        float2 A1 = __ldg(&pA[lane + 32]);
        float2 B0 = __ldg(&pB[lane]);
        float2 B1 = __ldg(&pB[lane + 32]);
        float gA0 = xla_logistic(__fadd_rn(k0, A0.x));
        float gA1 = xla_logistic(__fadd_rn(k1, A1.x));
        a0 = __fadd_rn(a0, __fmul_rn(gA0, A0.y));
        a1 = __fadd_rn(a1, __fmul_rn(gA1, A1.y));
        float gB0 = xla_logistic(__fadd_rn(k0, B0.x));
        float gB1 = xla_logistic(__fadd_rn(k1, B1.x));
        a0 = __fadd_rn(a0, __fmul_rn(gB0, B0.y));
        a1 = __fadd_rn(a1, __fmul_rn(gB1, B1.y));
    }
    if (e < end) {
        int sA = __ldg(&g_col[e]);
        const float2* pA = (const float2*)&g_qv[(size_t)sA * 128];
        float2 A0 = __ldg(&pA[lane]);
        float2 A1 = __ldg(&pA[lane + 32]);
        float gA0 = xla_logistic(__fadd_rn(k0, A0.x));
        float gA1 = xla_logistic(__fadd_rn(k1, A1.x));
        a0 = __fadd_rn(a0, __fmul_rn(gA0, A0.y));
        a1 = __fadd_rn(a1, __fmul_rn(gA1, A1.y));
    }
    float b0 = bias[lane], b1 = bias[lane + 32];
    g_h[base + lane]      = lrelu(__fadd_rn(__fadd_rn(g_s[base + lane], a0), b0));
    g_h[base + lane + 32] = lrelu(__fadd_rn(__fadd_rn(g_s[base + lane + 32], a1), b1));
}

// ---- output projection (FROZEN numerics) ----
__global__ __launch_bounds__(256) void out_gemm_kernel(
    const float* __restrict__ Wo, const float* __restrict__ bo, float* __restrict__ out)
{
    __shared__ float Ws[64 * 16];
    __shared__ float As[16][64];
    int tid = threadIdx.x;
    for (int idx = tid; idx < 64 * 16; idx += 256) Ws[idx] = Wo[idx];
    int row0 = blockIdx.x * 16;
    for (int idx = tid; idx < 16 * 64; idx += 256) {
        int r = idx >> 6, c = idx & 63;
        int node = row0 + r;
        As[r][c] = (node < NN) ? g_h[(size_t)node * 64 + c] : 0.f;
    }
    __syncthreads();
    int r = tid >> 4, c = tid & 15;
    float acc = 0.f;
#pragma unroll
    for (int k = 0; k < 64; k++) acc = __fmaf_rn(As[r][k], Ws[k * 16 + c], acc);
    int node = row0 + r;
    if (node < NN) out[(size_t)node * 16 + c] = __fadd_rn(acc, bo[c]);
}

extern "C" void kernel_launch(void* const* d_in, const int* in_sizes, int n_in,
                              void* d_out, int out_size)
{
    const float *x = 0, *W_in = 0, *b_in = 0, *W_h = 0, *b_h = 0, *W_out = 0, *b_out = 0;
    const int* ei = 0;
    for (int i = 0; i < n_in; i++) {
        switch (in_sizes[i]) {
            case 12800000: x = (const float*)d_in[i]; break;
            case 3200000: ei = (const int*)d_in[i]; break;
            case 32768: W_in = (const float*)d_in[i]; break;
            case 64: b_in = (const float*)d_in[i]; break;
            case 65536: W_h = (const float*)d_in[i]; break;
            case 256: b_h = (const float*)d_in[i]; break;
            case 1024: W_out = (const float*)d_in[i]; break;
            case 16: b_out = (const float*)d_in[i]; break;
        }
    }
    float* out = (float*)d_out;
    const int* src = ei;
    const int* dst = ei + EE;

    float* hptr = nullptr;
    cudaGetSymbolAddress((void**)&hptr, g_h);

    int tb = 256;
    zero_counts_kernel<<<(NN + tb - 1) / tb, tb>>>();
    hist_kernel<<<(EE + tb - 1) / tb, tb>>>(dst);
    int nb = (NN + 1023) / 1024;
    scan_block_kernel<<<nb, 1024>>>();
    scan_sums_kernel<<<1, 32>>>(nb);
    add_offsets_kernel<<<nb, 1024>>>();
    scatter_kernel<<<(EE + tb - 1) / tb, tb>>>(dst);
    sort_rows_kernel<<<(NN + tb - 1) / tb, tb>>>();
    remap_kernel<<<(EE + tb - 1) / tb, tb>>>(src);

    dim3 ggrid((NN + 31) / 32, 2);
    int eblocks = (NN * 32 + 255) / 256;

    gemm_kqvs_kernel<<<ggrid, 256>>>(x, FIN, W_in);
    edge_kernel<<<eblocks, 256>>>(b_in);
    for (int rep = 0; rep < 3; rep++)
        for (int l = 0; l < 4; l++) {
            gemm_kqvs_kernel<<<ggrid, 256>>>(hptr, HH, W_h + (size_t)l * 4 * HH * HH);
            edge_kernel<<<eblocks, 256>>>(b_h + l * HH);
        }
    out_gemm_kernel<<<(NN + 15) / 16, 256>>>(W_out, b_out, out);
}